// round 11
// baseline (speedup 1.0000x reference)
#include <cuda_runtime.h>
#include <cuda_fp16.h>
#include <cstdint>

// ============================================================================
// CESLayer: out[b,o] = cos( x@angle^T + bias ) * exp( x@log|w|^T )
// B=262144, I=O=128.  fp16 mma.sync (exact products):
//   angle = xh*angH + xl*angH + xh*angL ; logmag = xh*logH   (4 passes)
// R11: 32-row tiles; once-per-tile convert phase writes xh/xl fp16 panels
//      (k-loop A-side = ldmatrix, no per-warp cvt); cp.async staging hidden
//      under the k-loop. 16 warps = 2 row-blocks x 8 (wm x wn = 2 x 4).
// ============================================================================

#define N_TILES   8192            // 32-row tiles
#define GRID_CTAS 148
#define LDS_STRIDE 136

// smem byte offsets
// scratch f32: rb*17408            (32 rows x 136 f32 = 17408)
// panels:  34816 + rb*17408 : xh (8704) then xl (8704)
#define OFF_PAN  34816u
#define OFF_W    69632u           // 3 mats * 34816: [angH, angL, logH] fp16
#define OFF_BIAS 174080u
#define SMEM_BYTES 174592u

__device__ __align__(16) __half g_W[3 * 16384];

// ---------------------------------------------------------------------------
__device__ __forceinline__ uint32_t smem_u32(const void* p) {
    uint32_t a;
    asm("{ .reg .u64 t; cvta.to.shared.u64 t, %1; cvt.u32.u64 %0, t; }"
        : "=r"(a) : "l"(p));
    return a;
}

__device__ __forceinline__ uint32_t h2u(__half2 v) {
    return *reinterpret_cast<uint32_t*>(&v);
}

__device__ __forceinline__ void ldsm_x4(uint32_t r[4], uint32_t addr) {
    asm volatile("ldmatrix.sync.aligned.m8n8.x4.shared.b16 {%0,%1,%2,%3}, [%4];"
                 : "=r"(r[0]), "=r"(r[1]), "=r"(r[2]), "=r"(r[3]) : "r"(addr));
}

__device__ __forceinline__ void lds64(float2& p, uint32_t addr) {
    asm volatile("ld.shared.v2.f32 {%0,%1}, [%2];"
                 : "=f"(p.x), "=f"(p.y) : "r"(addr));
}

__device__ __forceinline__ void lds128(float4& v, uint32_t addr) {
    asm volatile("ld.shared.v4.f32 {%0,%1,%2,%3}, [%4];"
                 : "=f"(v.x), "=f"(v.y), "=f"(v.z), "=f"(v.w) : "r"(addr));
}

__device__ __forceinline__ void sts128(uint32_t addr, uint32_t r0, uint32_t r1,
                                       uint32_t r2, uint32_t r3) {
    asm volatile("st.shared.v4.b32 [%0], {%1,%2,%3,%4};"
                 :: "r"(addr), "r"(r0), "r"(r1), "r"(r2), "r"(r3) : "memory");
}

__device__ __forceinline__ void mma16816(float c[4], const uint32_t a[4],
                                         uint32_t b0, uint32_t b1) {
    asm volatile(
        "mma.sync.aligned.m16n8k16.row.col.f32.f16.f16.f32 "
        "{%0,%1,%2,%3}, {%4,%5,%6,%7}, {%8,%9}, {%0,%1,%2,%3};"
        : "+f"(c[0]), "+f"(c[1]), "+f"(c[2]), "+f"(c[3])
        : "r"(a[0]), "r"(a[1]), "r"(a[2]), "r"(a[3]), "r"(b0), "r"(b1));
}

// split one f32 pair into fp16 hi + lo packed halves
__device__ __forceinline__ void cvt_hl(float xx, float yy, uint32_t& h, uint32_t& l) {
    __half2 hh = __floats2half2_rn(xx, yy);
    __half2 ll = __floats2half2_rn(xx - __low2float(hh), yy - __high2float(hh));
    h = h2u(hh);
    l = h2u(ll);
}

#define GBAR256(id) asm volatile("bar.sync %0, 256;" :: "r"(id) : "memory")
#define CP_ASYNC16(dst, src) \
    asm volatile("cp.async.cg.shared.global [%0], [%1], 16;" :: "r"(dst), "l"(src))
#define CP_COMMIT() asm volatile("cp.async.commit_group;" ::: "memory")
#define CP_WAIT0()  asm volatile("cp.async.wait_group 0;" ::: "memory")

// ---------------------------------------------------------------------------
__global__ void ces_prep(const float* __restrict__ wr, const float* __restrict__ wi) {
    int idx = blockIdx.x * blockDim.x + threadIdx.x;
    if (idx >= 16384) return;
    float a = wr[idx], b = wi[idx];
    float la = 0.5f * logf(fmaf(a, a, b * b));
    float an = atan2f(b, a);
    __half anh = __float2half_rn(an);
    __half anl = __float2half_rn(an - __half2float(anh));
    g_W[0 * 16384 + idx] = anh;                   // angH
    g_W[1 * 16384 + idx] = anl;                   // angL
    g_W[2 * 16384 + idx] = __float2half_rn(la);   // logH
}

// ---------------------------------------------------------------------------
// 16 warps = 2 row-blocks x 8. Within block: wm = lwid&1 (16 rows),
// wn = lwid>>1 (32 cols). Warp tile 16x32.
// ---------------------------------------------------------------------------
__global__ void __launch_bounds__(512, 1)
ces_main(const float* __restrict__ x, const float* __restrict__ bias,
         float* __restrict__ out) {
    extern __shared__ char smem[];
    const uint32_t sb = smem_u32(smem);
    const int tid   = threadIdx.x;
    const int lane  = tid & 31;
    const int wid   = tid >> 5;
    const int rb    = wid >> 3;       // row-block 0/1
    const int lwid  = wid & 7;        // warp in block
    const int wm    = lwid & 1;
    const int wn    = lwid >> 1;
    const int rbtid = tid & 255;

    const uint32_t scratch = sb + (uint32_t)rb * 17408u;           // f32 32x136
    const uint32_t xh_base = sb + OFF_PAN + (uint32_t)rb * 17408u; // fp16 32x136
    const uint32_t xl_base = xh_base + 8704u;

    // ---- prologue: stage first tile's x (32 rows x 128 f32 = 1024 chunks) ----
    int tile = blockIdx.x * 2 + rb;
    if (tile < N_TILES) {
        const float* src = x + (size_t)tile * 32 * 128;
        #pragma unroll
        for (int j = 0; j < 4; ++j) {
            int chunk = j * 256 + rbtid;            // 0..1023
            CP_ASYNC16(scratch + (uint32_t)(chunk >> 5) * 544u + (uint32_t)(chunk & 31) * 16u,
                       src + (size_t)(chunk >> 5) * 128 + (chunk & 31) * 4);
        }
        CP_COMMIT();
    }

    // ---- copy W (3 x 128 x 128 fp16) into padded smem ----
    for (int r = tid; r < 384; r += 512) {
        const uint4* srcw = (const uint4*)(g_W + r * 128);
        uint4* dst = (uint4*)(smem + OFF_W + ((uint32_t)(r >> 7) * 17408u +
                                              (uint32_t)(r & 127) * LDS_STRIDE) * 2u);
        #pragma unroll
        for (int j = 0; j < 16; ++j) dst[j] = srcw[j];
    }
    if (tid < 128) ((float*)(smem + OFF_BIAS))[tid] = bias[tid];
    __syncthreads();

    // convert-phase addressing: row = rbtid>>3, cols (rbtid&7)*16 .. +15
    const int cv_row = rbtid >> 3;
    const int cv_c0  = (rbtid & 7) * 16;
    const uint32_t cv_src = scratch + (uint32_t)cv_row * 544u + (uint32_t)cv_c0 * 4u;
    const uint32_t cv_dh  = xh_base + (uint32_t)cv_row * 272u + (uint32_t)cv_c0 * 2u;
    const uint32_t cv_dl  = xl_base + (uint32_t)cv_row * 272u + (uint32_t)cv_c0 * 2u;

    // A-side ldmatrix offset (fp16 panels)
    const uint32_t aoff = ((uint32_t)(wm * 16 + (lane & 15)) * LDS_STRIDE +
                           (uint32_t)((lane >> 4) * 8)) * 2u;
    const uint32_t a_h = xh_base + aoff;
    const uint32_t a_l = xl_base + aoff;

    // B-side ldmatrix bases
    const int colbase = wn * 32;
    const uint32_t boff = ((uint32_t)(colbase + ((lane & 7) | ((lane & 16) >> 1))) * LDS_STRIDE +
                          (uint32_t)(lane & 8)) * 2u;
    const uint32_t MI_W = 16u * LDS_STRIDE * 2u;
    const uint32_t wbA = sb + OFF_W + boff;           // angH
    const uint32_t wbL = wbA + 34816u;                // angL
    const uint32_t wbG = wbA + 69632u;                // logH

    const int bar_id = rb + 1;

    for (; tile < N_TILES; tile += 2 * GRID_CTAS) {
        CP_WAIT0();
        GBAR256(bar_id);   // scratch complete & visible; prev k-loop reads done

        // ---- convert f32 scratch -> xh/xl fp16 panels (once per tile) ----
        {
            float4 a0, a1, a2, a3;
            lds128(a0, cv_src);
            lds128(a1, cv_src + 16u);
            lds128(a2, cv_src + 32u);
            lds128(a3, cv_src + 48u);
            uint32_t h[8], l[8];
            cvt_hl(a0.x, a0.y, h[0], l[0]);
            cvt_hl(a0.z, a0.w, h[1], l[1]);
            cvt_hl(a1.x, a1.y, h[2], l[2]);
            cvt_hl(a1.z, a1.w, h[3], l[3]);
            cvt_hl(a2.x, a2.y, h[4], l[4]);
            cvt_hl(a2.z, a2.w, h[5], l[5]);
            cvt_hl(a3.x, a3.y, h[6], l[6]);
            cvt_hl(a3.z, a3.w, h[7], l[7]);
            sts128(cv_dh,       h[0], h[1], h[2], h[3]);
            sts128(cv_dh + 16u, h[4], h[5], h[6], h[7]);
            sts128(cv_dl,       l[0], l[1], l[2], l[3]);
            sts128(cv_dl + 16u, l[4], l[5], l[6], l[7]);
        }
        GBAR256(bar_id);   // panels ready; scratch free

        // ---- stage next tile's f32 (latency hidden under k-loop) ----
        {
            int nxt = tile + 2 * GRID_CTAS;
            if (nxt < N_TILES) {
                const float* src = x + (size_t)nxt * 32 * 128;
                #pragma unroll
                for (int j = 0; j < 4; ++j) {
                    int chunk = j * 256 + rbtid;
                    CP_ASYNC16(scratch + (uint32_t)(chunk >> 5) * 544u +
                                   (uint32_t)(chunk & 31) * 16u,
                               src + (size_t)(chunk >> 5) * 128 + (chunk & 31) * 4);
                }
                CP_COMMIT();
            }
        }

        // ---- k-loop ----
        float acc[2][4][4];   // [mat(log/ang)][nc][4]
        #pragma unroll
        for (int m = 0; m < 2; ++m)
            #pragma unroll
            for (int n = 0; n < 4; ++n)
                #pragma unroll
                for (int q = 0; q < 4; ++q) acc[m][n][q] = 0.f;

        #pragma unroll
        for (int k = 0; k < 8; ++k) {
            const uint32_t kw = (uint32_t)k * 32u;

            uint32_t ah[4], al[4];
            ldsm_x4(ah, a_h + kw);
            ldsm_x4(al, a_l + kw);

            uint32_t bA[2][4];
            ldsm_x4(bA[0], wbA + kw);
            ldsm_x4(bA[1], wbA + MI_W + kw);

            // pass 1: ang += xh * angH
            #pragma unroll
            for (int h = 0; h < 2; ++h)
                #pragma unroll
                for (int q = 0; q < 2; ++q)
                    mma16816(acc[1][h * 2 + q], ah, bA[h][2 * q], bA[h][2 * q + 1]);

            // pass 2: log += xh * logH
            {
                uint32_t bG[2][4];
                ldsm_x4(bG[0], wbG + kw);
                ldsm_x4(bG[1], wbG + MI_W + kw);
                #pragma unroll
                for (int h = 0; h < 2; ++h)
                    #pragma unroll
                    for (int q = 0; q < 2; ++q)
                        mma16816(acc[0][h * 2 + q], ah, bG[h][2 * q], bG[h][2 * q + 1]);
            }

            // pass 3: ang += xl * angH
            #pragma unroll
            for (int h = 0; h < 2; ++h)
                #pragma unroll
                for (int q = 0; q < 2; ++q)
                    mma16816(acc[1][h * 2 + q], al, bA[h][2 * q], bA[h][2 * q + 1]);

            // pass 4: ang += xh * angL
            {
                uint32_t bL[2][4];
                ldsm_x4(bL[0], wbL + kw);
                ldsm_x4(bL[1], wbL + MI_W + kw);
                #pragma unroll
                for (int h = 0; h < 2; ++h)
                    #pragma unroll
                    for (int q = 0; q < 2; ++q)
                        mma16816(acc[1][h * 2 + q], ah, bL[h][2 * q], bL[h][2 * q + 1]);
            }
        }

        // ---- epilogue: out = cos(ang + bias) * exp(log) ----
        {
            size_t r0 = (size_t)tile * 32 + wm * 16 + (lane >> 2);
            float* p0 = out + r0 * 128 + colbase + 2 * (lane & 3);
            #pragma unroll
            for (int nc = 0; nc < 4; ++nc) {
                float2 bb;
                lds64(bb, sb + OFF_BIAS +
                          (uint32_t)(colbase + nc * 8 + 2 * (lane & 3)) * 4u);
                const float* A = acc[1][nc];
                const float* G = acc[0][nc];
                float2 o0, o1;
                o0.x = __cosf(A[0] + bb.x) * __expf(G[0]);
                o0.y = __cosf(A[1] + bb.y) * __expf(G[1]);
                o1.x = __cosf(A[2] + bb.x) * __expf(G[2]);
                o1.y = __cosf(A[3] + bb.y) * __expf(G[3]);
                *(float2*)(p0 + nc * 8) = o0;
                *(float2*)(p0 + nc * 8 + 8 * 128) = o1;
            }
        }
    }
}

// ---------------------------------------------------------------------------
extern "C" void kernel_launch(void* const* d_in, const int* in_sizes, int n_in,
                              void* d_out, int out_size) {
    const float* x    = (const float*)d_in[0];
    const float* wr   = (const float*)d_in[1];
    const float* wi   = (const float*)d_in[2];
    const float* bias = (const float*)d_in[3];
    float* out = (float*)d_out;
    (void)in_sizes; (void)n_in; (void)out_size;

    cudaFuncSetAttribute(ces_main, cudaFuncAttributeMaxDynamicSharedMemorySize,
                         (int)SMEM_BYTES);

    ces_prep<<<64, 256>>>(wr, wi);
    ces_main<<<GRID_CTAS, 512, SMEM_BYTES>>>(x, bias, out);
}

// round 14
// speedup vs baseline: 1.0586x; 1.0586x over previous
#include <cuda_runtime.h>
#include <cuda_fp16.h>
#include <cstdint>

// ============================================================================
// CESLayer: out[b,o] = cos( x@angle^T + bias ) * exp( x@log|w|^T )
// B=262144, I=O=128.  fp16 mma.sync (exact products):
//   angle = xh*angH + xl*angH + xh*angL ; logmag = xh*logH   (4 passes)
// R12: R10 tiling (4 groups x 4 warps, 32x32 warp tiles, 64-row blocks)
//      + once-per-tile panel conversion (k-loop A-side = ldmatrix only)
//      + in-place region reuse: f32 staging overwrites fp16 panels after the
//        k-loop (GBAR-ordered), cp.async latency hidden under the epilogue.
// ============================================================================

#define N_TILES   4096            // 64-row tiles
#define GRID_CTAS 148
#define LDS_STRIDE 136

// smem: region rb at rb*34816 (f32 scratch 64x136 OR fp16 panels xh/xl 64x136)
#define OFF_W    69632u           // 3 mats * 34816: [angH, angL, logH] fp16
#define OFF_BIAS 174080u
#define SMEM_BYTES 174592u

__device__ __align__(16) __half g_W[3 * 16384];

// ---------------------------------------------------------------------------
__device__ __forceinline__ uint32_t smem_u32(const void* p) {
    uint32_t a;
    asm("{ .reg .u64 t; cvta.to.shared.u64 t, %1; cvt.u32.u64 %0, t; }"
        : "=r"(a) : "l"(p));
    return a;
}

__device__ __forceinline__ uint32_t h2u(__half2 v) {
    return *reinterpret_cast<uint32_t*>(&v);
}

__device__ __forceinline__ void ldsm_x4(uint32_t r[4], uint32_t addr) {
    asm volatile("ldmatrix.sync.aligned.m8n8.x4.shared.b16 {%0,%1,%2,%3}, [%4];"
                 : "=r"(r[0]), "=r"(r[1]), "=r"(r[2]), "=r"(r[3]) : "r"(addr));
}

__device__ __forceinline__ void lds64(float2& p, uint32_t addr) {
    asm volatile("ld.shared.v2.f32 {%0,%1}, [%2];"
                 : "=f"(p.x), "=f"(p.y) : "r"(addr));
}

__device__ __forceinline__ void lds128(float4& v, uint32_t addr) {
    asm volatile("ld.shared.v4.f32 {%0,%1,%2,%3}, [%4];"
                 : "=f"(v.x), "=f"(v.y), "=f"(v.z), "=f"(v.w) : "r"(addr));
}

__device__ __forceinline__ void sts64(uint32_t addr, uint32_t r0, uint32_t r1) {
    asm volatile("st.shared.v2.b32 [%0], {%1,%2};"
                 :: "r"(addr), "r"(r0), "r"(r1) : "memory");
}

__device__ __forceinline__ void mma16816(float c[4], const uint32_t a[4],
                                         uint32_t b0, uint32_t b1) {
    asm volatile(
        "mma.sync.aligned.m16n8k16.row.col.f32.f16.f16.f32 "
        "{%0,%1,%2,%3}, {%4,%5,%6,%7}, {%8,%9}, {%0,%1,%2,%3};"
        : "+f"(c[0]), "+f"(c[1]), "+f"(c[2]), "+f"(c[3])
        : "r"(a[0]), "r"(a[1]), "r"(a[2]), "r"(a[3]), "r"(b0), "r"(b1));
}

// split one f32 pair into fp16 hi + lo packed halves
__device__ __forceinline__ void cvt_hl(float xx, float yy, uint32_t& h, uint32_t& l) {
    __half2 hh = __floats2half2_rn(xx, yy);
    __half2 ll = __floats2half2_rn(xx - __low2float(hh), yy - __high2float(hh));
    h = h2u(hh);
    l = h2u(ll);
}

#define GBAR256(id) asm volatile("bar.sync %0, 256;" :: "r"(id) : "memory")
#define CP_ASYNC16(dst, src) \
    asm volatile("cp.async.cg.shared.global [%0], [%1], 16;" :: "r"(dst), "l"(src))
#define CP_COMMIT() asm volatile("cp.async.commit_group;" ::: "memory")
#define CP_WAIT0()  asm volatile("cp.async.wait_group 0;" ::: "memory")

// ---------------------------------------------------------------------------
__global__ void ces_prep(const float* __restrict__ wr, const float* __restrict__ wi) {
    int idx = blockIdx.x * blockDim.x + threadIdx.x;
    if (idx >= 16384) return;
    float a = wr[idx], b = wi[idx];
    float la = 0.5f * logf(fmaf(a, a, b * b));
    float an = atan2f(b, a);
    __half anh = __float2half_rn(an);
    __half anl = __float2half_rn(an - __half2float(anh));
    g_W[0 * 16384 + idx] = anh;                   // angH
    g_W[1 * 16384 + idx] = anl;                   // angL
    g_W[2 * 16384 + idx] = __float2half_rn(la);   // logH
}

// ---------------------------------------------------------------------------
// 16 warps = 4 groups x 4. Group g: row-block rb=g>>1 (64 rows), N-half nh=g&1.
// Within group: wm = lwid&1 (32 rows), wn = lwid>>1 (32 cols).
// ---------------------------------------------------------------------------
__global__ void __launch_bounds__(512, 1)
ces_main(const float* __restrict__ x, const float* __restrict__ bias,
         float* __restrict__ out) {
    extern __shared__ char smem[];
    const uint32_t sb = smem_u32(smem);
    const int tid   = threadIdx.x;
    const int lane  = tid & 31;
    const int wid   = tid >> 5;
    const int g     = wid >> 2;
    const int lwid  = wid & 3;
    const int rb    = g >> 1;         // row-block 0/1
    const int nh    = g & 1;          // N-half
    const int wm    = lwid & 1;
    const int wn    = lwid >> 1;
    const int rbtid = tid & 255;      // thread id within row-block

    const uint32_t region  = sb + (uint32_t)rb * 34816u;   // f32 scratch OR panels
    const uint32_t xh_base = region;                       // fp16 64x136
    const uint32_t xl_base = region + 17408u;

    // ---- prologue: stage first tile's x f32 (2048 x 16B chunks) ----
    int tile = blockIdx.x * 2 + rb;
    if (tile < N_TILES) {
        const float* src = x + (size_t)tile * 64 * 128;
        #pragma unroll
        for (int j = 0; j < 8; ++j) {
            int chunk = j * 256 + rbtid;            // 0..2047
            CP_ASYNC16(region + (uint32_t)(chunk >> 5) * 544u + (uint32_t)(chunk & 31) * 16u,
                       src + (size_t)(chunk >> 5) * 128 + (chunk & 31) * 4);
        }
        CP_COMMIT();
    }

    // ---- copy W (3 x 128 x 128 fp16) into padded smem ----
    for (int r = tid; r < 384; r += 512) {
        const uint4* srcw = (const uint4*)(g_W + r * 128);
        uint4* dst = (uint4*)(smem + OFF_W + ((uint32_t)(r >> 7) * 17408u +
                                              (uint32_t)(r & 127) * LDS_STRIDE) * 2u);
        #pragma unroll
        for (int j = 0; j < 16; ++j) dst[j] = srcw[j];
    }
    if (tid < 128) ((float*)(smem + OFF_BIAS))[tid] = bias[tid];
    CP_WAIT0();
    __syncthreads();

    // convert mapping: row = rbtid>>2 (0..63), chunks c = (rbtid&3) + 4i
    const int cv_row = rbtid >> 2;
    const int cv_cb  = rbtid & 3;
    const uint32_t cv_src = region + (uint32_t)cv_row * 544u + (uint32_t)cv_cb * 16u;
    const uint32_t cv_dh  = region + (uint32_t)cv_row * 272u + (uint32_t)cv_cb * 8u;

    const int bar_id = rb + 1;

    // ---- prologue convert: f32 -> xh/xl panels (in place) ----
    if (tile < N_TILES) {
        float4 v[8];
        #pragma unroll
        for (int i = 0; i < 8; ++i) lds128(v[i], cv_src + (uint32_t)i * 64u);
        GBAR256(bar_id);
        #pragma unroll
        for (int i = 0; i < 8; ++i) {
            uint32_t h0, l0, h1, l1;
            cvt_hl(v[i].x, v[i].y, h0, l0);
            cvt_hl(v[i].z, v[i].w, h1, l1);
            sts64(cv_dh + (uint32_t)i * 32u,           h0, h1);
            sts64(cv_dh + 17408u + (uint32_t)i * 32u,  l0, l1);
        }
        GBAR256(bar_id);
    }

    // A-side ldmatrix bases (fp16 panels, 136 stride)
    const uint32_t aoff = ((uint32_t)(wm * 32 + (lane & 15)) * LDS_STRIDE +
                           (uint32_t)((lane >> 4) * 8)) * 2u;
    const uint32_t a_h  = xh_base + aoff;
    const uint32_t a_l  = xl_base + aoff;
    const uint32_t MI_A = 16u * LDS_STRIDE * 2u;     // +16 rows (fp16)

    // B-side ldmatrix bases
    const int colbase = nh * 64 + wn * 32;
    const uint32_t boff = ((uint32_t)(colbase + ((lane & 7) | ((lane & 16) >> 1))) * LDS_STRIDE +
                          (uint32_t)(lane & 8)) * 2u;
    const uint32_t MI_W = 16u * LDS_STRIDE * 2u;
    const uint32_t wbA = sb + OFF_W + boff;           // angH
    const uint32_t wbL = wbA + 34816u;                // angL
    const uint32_t wbG = wbA + 69632u;                // logH

    for (; tile < N_TILES; tile += 2 * GRID_CTAS) {
        float acc[2][2][4][4];   // [mat(log/ang)][mi][nc][4]
        #pragma unroll
        for (int m = 0; m < 2; ++m)
            #pragma unroll
            for (int i = 0; i < 2; ++i)
                #pragma unroll
                for (int n = 0; n < 4; ++n)
                    #pragma unroll
                    for (int q = 0; q < 4; ++q) acc[m][i][n][q] = 0.f;

        // ---- k-loop: 10 ldsm + 32 HMMA per k ----
        #pragma unroll
        for (int k = 0; k < 8; ++k) {
            const uint32_t kw = (uint32_t)k * 32u;

            uint32_t ah[2][4], al[2][4];
            ldsm_x4(ah[0], a_h + kw);
            ldsm_x4(ah[1], a_h + MI_A + kw);
            ldsm_x4(al[0], a_l + kw);
            ldsm_x4(al[1], a_l + MI_A + kw);

            uint32_t bA[2][4];
            ldsm_x4(bA[0], wbA + kw);
            ldsm_x4(bA[1], wbA + MI_W + kw);

            // pass 1: ang += xh * angH
            #pragma unroll
            for (int h = 0; h < 2; ++h)
                #pragma unroll
                for (int q = 0; q < 2; ++q) {
                    mma16816(acc[1][0][h * 2 + q], ah[0], bA[h][2 * q], bA[h][2 * q + 1]);
                    mma16816(acc[1][1][h * 2 + q], ah[1], bA[h][2 * q], bA[h][2 * q + 1]);
                }

            // pass 2: log += xh * logH
            {
                uint32_t bG[2][4];
                ldsm_x4(bG[0], wbG + kw);
                ldsm_x4(bG[1], wbG + MI_W + kw);
                #pragma unroll
                for (int h = 0; h < 2; ++h)
                    #pragma unroll
                    for (int q = 0; q < 2; ++q) {
                        mma16816(acc[0][0][h * 2 + q], ah[0], bG[h][2 * q], bG[h][2 * q + 1]);
                        mma16816(acc[0][1][h * 2 + q], ah[1], bG[h][2 * q], bG[h][2 * q + 1]);
                    }
            }

            // pass 3: ang += xl * angH
            #pragma unroll
            for (int h = 0; h < 2; ++h)
                #pragma unroll
                for (int q = 0; q < 2; ++q) {
                    mma16816(acc[1][0][h * 2 + q], al[0], bA[h][2 * q], bA[h][2 * q + 1]);
                    mma16816(acc[1][1][h * 2 + q], al[1], bA[h][2 * q], bA[h][2 * q + 1]);
                }

            // pass 4: ang += xh * angL
            {
                uint32_t bL[2][4];
                ldsm_x4(bL[0], wbL + kw);
                ldsm_x4(bL[1], wbL + MI_W + kw);
                #pragma unroll
                for (int h = 0; h < 2; ++h)
                    #pragma unroll
                    for (int q = 0; q < 2; ++q) {
                        mma16816(acc[1][0][h * 2 + q], ah[0], bL[h][2 * q], bL[h][2 * q + 1]);
                        mma16816(acc[1][1][h * 2 + q], ah[1], bL[h][2 * q], bL[h][2 * q + 1]);
                    }
            }
        }

        GBAR256(bar_id);   // all 8 row-block warps done reading panels

        // ---- stage next tile's f32 over the panels (hidden under epilogue) --
        const int nxt = tile + 2 * GRID_CTAS;
        if (nxt < N_TILES) {
            const float* src = x + (size_t)nxt * 64 * 128;
            #pragma unroll
            for (int j = 0; j < 8; ++j) {
                int chunk = j * 256 + rbtid;
                CP_ASYNC16(region + (uint32_t)(chunk >> 5) * 544u +
                               (uint32_t)(chunk & 31) * 16u,
                           src + (size_t)(chunk >> 5) * 128 + (chunk & 31) * 4);
            }
            CP_COMMIT();
        }

        // ---- epilogue: out = cos(ang + bias) * exp(log) ----
        #pragma unroll
        for (int mi = 0; mi < 2; ++mi) {
            size_t r0 = (size_t)tile * 64 + wm * 32 + mi * 16 + (lane >> 2);
            float* p0 = out + r0 * 128 + colbase + 2 * (lane & 3);
            #pragma unroll
            for (int nc = 0; nc < 4; ++nc) {
                float2 bb;
                lds64(bb, sb + OFF_BIAS +
                          (uint32_t)(colbase + nc * 8 + 2 * (lane & 3)) * 4u);
                const float* A = acc[1][mi][nc];
                const float* G = acc[0][mi][nc];
                float2 o0, o1;
                o0.x = __cosf(A[0] + bb.x) * __expf(G[0]);
                o0.y = __cosf(A[1] + bb.y) * __expf(G[1]);
                o1.x = __cosf(A[2] + bb.x) * __expf(G[2]);
                o1.y = __cosf(A[3] + bb.y) * __expf(G[3]);
                *(float2*)(p0 + nc * 8) = o0;
                *(float2*)(p0 + nc * 8 + 8 * 128) = o1;
            }
        }

        // ---- convert next tile in place: read all, barrier, write all ----
        if (nxt < N_TILES) {
            CP_WAIT0();
            GBAR256(bar_id);   // staged f32 visible to all row-block threads
            float4 v[8];
            #pragma unroll
            for (int i = 0; i < 8; ++i) lds128(v[i], cv_src + (uint32_t)i * 64u);
            GBAR256(bar_id);   // all reads done before in-place writes
            #pragma unroll
            for (int i = 0; i < 8; ++i) {
                uint32_t h0, l0, h1, l1;
                cvt_hl(v[i].x, v[i].y, h0, l0);
                cvt_hl(v[i].z, v[i].w, h1, l1);
                sts64(cv_dh + (uint32_t)i * 32u,          h0, h1);
                sts64(cv_dh + 17408u + (uint32_t)i * 32u, l0, l1);
            }
            GBAR256(bar_id);   // panels ready
        }
    }
}

// ---------------------------------------------------------------------------
extern "C" void kernel_launch(void* const* d_in, const int* in_sizes, int n_in,
                              void* d_out, int out_size) {
    const float* x    = (const float*)d_in[0];
    const float* wr   = (const float*)d_in[1];
    const float* wi   = (const float*)d_in[2];
    const float* bias = (const float*)d_in[3];
    float* out = (float*)d_out;
    (void)in_sizes; (void)n_in; (void)out_size;

    cudaFuncSetAttribute(ces_main, cudaFuncAttributeMaxDynamicSharedMemorySize,
                         (int)SMEM_BYTES);

    ces_prep<<<64, 256>>>(wr, wi);
    ces_main<<<GRID_CTAS, 512, SMEM_BYTES>>>(x, bias, out);
}

// round 15
// speedup vs baseline: 1.1341x; 1.0713x over previous
#include <cuda_runtime.h>
#include <cuda_fp16.h>
#include <cstdint>

// ============================================================================
// CESLayer: out[b,o] = cos( x@angle^T + bias ) * exp( x@log|w|^T )
// B=262144, I=O=128.  fp16 mma.sync (exact products):
//   angle = xh*angH + xl*angH + xh*angL ; logmag = xh*logH   (4 passes)
// R13: 384 threads = 3 row-blocks x 4 warps, 32-row tiles, 32x32 warp tiles.
//      Per rb: f32 scratch (cp.async) + xh/xl fp16 panels. Convert is a tiny
//      once-per-tile step; NO barrier between epilogue and next k-loop, so
//      warps drift and MUFU epilogue hides under other warps' HMMA.
// ============================================================================

#define N_TILES   8192            // 32-row tiles
#define GRID_CTAS 148
#define N_RB      3
#define TILE_STRIDE (N_RB * GRID_CTAS)    // 444
#define LDS_STRIDE 136

// per-rb block: scratch 16384 (32x128 f32 unpadded) + panels 17408 (hi|lo 8704)
#define RB_BYTES  33792u
#define OFF_W     101376u         // 3 mats * 34816: [angH, angL, logH] fp16
#define OFF_BIAS  205824u
#define SMEM_BYTES 206336u

__device__ __align__(16) __half g_W[3 * 16384];

// ---------------------------------------------------------------------------
__device__ __forceinline__ uint32_t smem_u32(const void* p) {
    uint32_t a;
    asm("{ .reg .u64 t; cvta.to.shared.u64 t, %1; cvt.u32.u64 %0, t; }"
        : "=r"(a) : "l"(p));
    return a;
}

__device__ __forceinline__ uint32_t h2u(__half2 v) {
    return *reinterpret_cast<uint32_t*>(&v);
}

__device__ __forceinline__ void ldsm_x4(uint32_t r[4], uint32_t addr) {
    asm volatile("ldmatrix.sync.aligned.m8n8.x4.shared.b16 {%0,%1,%2,%3}, [%4];"
                 : "=r"(r[0]), "=r"(r[1]), "=r"(r[2]), "=r"(r[3]) : "r"(addr));
}

__device__ __forceinline__ void lds128(float4& v, uint32_t addr) {
    asm volatile("ld.shared.v4.f32 {%0,%1,%2,%3}, [%4];"
                 : "=f"(v.x), "=f"(v.y), "=f"(v.z), "=f"(v.w) : "r"(addr));
}

__device__ __forceinline__ void sts64(uint32_t addr, uint32_t r0, uint32_t r1) {
    asm volatile("st.shared.v2.b32 [%0], {%1,%2};"
                 :: "r"(addr), "r"(r0), "r"(r1) : "memory");
}

__device__ __forceinline__ void mma16816(float c[4], const uint32_t a[4],
                                         uint32_t b0, uint32_t b1) {
    asm volatile(
        "mma.sync.aligned.m16n8k16.row.col.f32.f16.f16.f32 "
        "{%0,%1,%2,%3}, {%4,%5,%6,%7}, {%8,%9}, {%0,%1,%2,%3};"
        : "+f"(c[0]), "+f"(c[1]), "+f"(c[2]), "+f"(c[3])
        : "r"(a[0]), "r"(a[1]), "r"(a[2]), "r"(a[3]), "r"(b0), "r"(b1));
}

// split one f32 pair into fp16 hi + lo packed halves
__device__ __forceinline__ void cvt_hl(float xx, float yy, uint32_t& h, uint32_t& l) {
    __half2 hh = __floats2half2_rn(xx, yy);
    __half2 ll = __floats2half2_rn(xx - __low2float(hh), yy - __high2float(hh));
    h = h2u(hh);
    l = h2u(ll);
}

#define GBAR128(id) asm volatile("bar.sync %0, 128;" :: "r"(id) : "memory")
#define CP_ASYNC16(dst, src) \
    asm volatile("cp.async.cg.shared.global [%0], [%1], 16;" :: "r"(dst), "l"(src))
#define CP_COMMIT() asm volatile("cp.async.commit_group;" ::: "memory")
#define CP_WAIT0()  asm volatile("cp.async.wait_group 0;" ::: "memory")

// ---------------------------------------------------------------------------
__global__ void ces_prep(const float* __restrict__ wr, const float* __restrict__ wi) {
    int idx = blockIdx.x * blockDim.x + threadIdx.x;
    if (idx >= 16384) return;
    float a = wr[idx], b = wi[idx];
    float la = 0.5f * logf(fmaf(a, a, b * b));
    float an = atan2f(b, a);
    __half anh = __float2half_rn(an);
    __half anl = __float2half_rn(an - __half2float(anh));
    g_W[0 * 16384 + idx] = anh;                   // angH
    g_W[1 * 16384 + idx] = anl;                   // angL
    g_W[2 * 16384 + idx] = __float2half_rn(la);   // logH
}

// ---------------------------------------------------------------------------
// 12 warps = 3 row-blocks x 4 warps. rb tile: 32 rows x 128 cols.
// Warp: wn = wid&3 (32-col slice); warp tile 32x32 (mi covers rows).
// ---------------------------------------------------------------------------
__global__ void __launch_bounds__(384, 1)
ces_main(const float* __restrict__ x, const float* __restrict__ bias,
         float* __restrict__ out) {
    extern __shared__ char smem[];
    const uint32_t sb = smem_u32(smem);
    const int tid   = threadIdx.x;
    const int lane  = tid & 31;
    const int wid   = tid >> 5;
    const int rb    = wid >> 2;       // row-block 0..2
    const int wn    = wid & 3;        // 32-col slice
    const int rbtid = tid & 127;      // thread id within row-block

    const uint32_t scratch = sb + (uint32_t)rb * RB_BYTES;   // f32 32x128
    const uint32_t xh_base = scratch + 16384u;               // fp16 32x136
    const uint32_t xl_base = xh_base + 8704u;

    // ---- prologue: stage first tile's x (1024 x 16B chunks per rb) ----
    int tile = blockIdx.x * N_RB + rb;
    if (tile < N_TILES) {
        const float* src = x + (size_t)tile * 32 * 128;
        #pragma unroll
        for (int j = 0; j < 8; ++j) {
            int chunk = j * 128 + rbtid;            // 0..1023
            CP_ASYNC16(scratch + (uint32_t)chunk * 16u, src + (size_t)chunk * 4);
        }
        CP_COMMIT();
    }

    // ---- copy W (3 x 128 x 128 fp16) into padded smem ----
    {
        int r = tid;   // 384 rows, 384 threads: one row each
        const uint4* srcw = (const uint4*)(g_W + r * 128);
        uint4* dst = (uint4*)(smem + OFF_W + ((uint32_t)(r >> 7) * 17408u +
                                              (uint32_t)(r & 127) * LDS_STRIDE) * 2u);
        #pragma unroll
        for (int j = 0; j < 16; ++j) dst[j] = srcw[j];
    }
    if (tid < 128) ((float*)(smem + OFF_BIAS))[tid] = bias[tid];
    CP_WAIT0();
    __syncthreads();

    // bias pairs in registers (tile-invariant)
    const int colbase = wn * 32;
    float bs0[4], bs1[4];
    {
        const float* sbias = (const float*)(smem + OFF_BIAS);
        #pragma unroll
        for (int nc = 0; nc < 4; ++nc) {
            int c = colbase + nc * 8 + 2 * (lane & 3);
            bs0[nc] = sbias[c];
            bs1[nc] = sbias[c + 1];
        }
    }

    // convert mapping: row = rbtid>>2 (0..31); chunk c = c0 + 4i (mod 32),
    // c0 parity-shifted for conflict-free lds128 phases.
    const uint32_t cv_row = (uint32_t)(rbtid >> 2);
    const uint32_t cv_c0  = (uint32_t)((rbtid & 3) | ((cv_row & 1u) << 2));

    const int bar_id = rb + 1;

    // ---- prologue: convert tile -> panels; stage tile+stride ----
    if (tile < N_TILES) {
        #pragma unroll
        for (int i = 0; i < 8; ++i) {
            uint32_t c = (cv_c0 + 4u * (uint32_t)i) & 31u;
            float4 v;
            lds128(v, scratch + (cv_row * 32u + c) * 16u);
            uint32_t h0, l0, h1, l1;
            cvt_hl(v.x, v.y, h0, l0);
            cvt_hl(v.z, v.w, h1, l1);
            uint32_t d = cv_row * 272u + c * 8u;
            sts64(xh_base + d, h0, h1);
            sts64(xl_base + d, l0, l1);
        }
        GBAR128(bar_id);
        int nxt = tile + TILE_STRIDE;
        if (nxt < N_TILES) {
            const float* src = x + (size_t)nxt * 32 * 128;
            #pragma unroll
            for (int j = 0; j < 8; ++j) {
                int chunk = j * 128 + rbtid;
                CP_ASYNC16(scratch + (uint32_t)chunk * 16u, src + (size_t)chunk * 4);
            }
            CP_COMMIT();
        }
    }

    // A-side ldmatrix bases (panels, 136 fp16 stride)
    const uint32_t aoff = ((uint32_t)(lane & 15) * LDS_STRIDE +
                           (uint32_t)((lane >> 4) * 8)) * 2u;
    const uint32_t a_h  = xh_base + aoff;
    const uint32_t a_l  = xl_base + aoff;
    const uint32_t MI_A = 16u * LDS_STRIDE * 2u;

    // B-side ldmatrix bases
    const uint32_t boff = ((uint32_t)(colbase + ((lane & 7) | ((lane & 16) >> 1))) * LDS_STRIDE +
                          (uint32_t)(lane & 8)) * 2u;
    const uint32_t MI_W = 16u * LDS_STRIDE * 2u;
    const uint32_t wbA = sb + OFF_W + boff;           // angH
    const uint32_t wbL = wbA + 34816u;                // angL
    const uint32_t wbG = wbA + 69632u;                // logH

    for (; tile < N_TILES; tile += TILE_STRIDE) {
        float acc[2][2][4][4];   // [mat(log/ang)][mi][nc][4]
        #pragma unroll
        for (int m = 0; m < 2; ++m)
            #pragma unroll
            for (int i = 0; i < 2; ++i)
                #pragma unroll
                for (int n = 0; n < 4; ++n)
                    #pragma unroll
                    for (int q = 0; q < 4; ++q) acc[m][i][n][q] = 0.f;

        // ---- k-loop: 10 ldsm + 32 HMMA per k (verified R10 pass order) ----
        #pragma unroll
        for (int k = 0; k < 8; ++k) {
            const uint32_t kw = (uint32_t)k * 32u;

            uint32_t ah[2][4], al[2][4];
            ldsm_x4(ah[0], a_h + kw);
            ldsm_x4(ah[1], a_h + MI_A + kw);
            ldsm_x4(al[0], a_l + kw);
            ldsm_x4(al[1], a_l + MI_A + kw);

            uint32_t bA[2][4];
            ldsm_x4(bA[0], wbA + kw);
            ldsm_x4(bA[1], wbA + MI_W + kw);

            // pass 1: ang += xh * angH
            #pragma unroll
            for (int h = 0; h < 2; ++h)
                #pragma unroll
                for (int q = 0; q < 2; ++q) {
                    mma16816(acc[1][0][h * 2 + q], ah[0], bA[h][2 * q], bA[h][2 * q + 1]);
                    mma16816(acc[1][1][h * 2 + q], ah[1], bA[h][2 * q], bA[h][2 * q + 1]);
                }

            // pass 2: log += xh * logH
            {
                uint32_t bG[2][4];
                ldsm_x4(bG[0], wbG + kw);
                ldsm_x4(bG[1], wbG + MI_W + kw);
                #pragma unroll
                for (int h = 0; h < 2; ++h)
                    #pragma unroll
                    for (int q = 0; q < 2; ++q) {
                        mma16816(acc[0][0][h * 2 + q], ah[0], bG[h][2 * q], bG[h][2 * q + 1]);
                        mma16816(acc[0][1][h * 2 + q], ah[1], bG[h][2 * q], bG[h][2 * q + 1]);
                    }
            }

            // pass 3: ang += xl * angH
            #pragma unroll
            for (int h = 0; h < 2; ++h)
                #pragma unroll
                for (int q = 0; q < 2; ++q) {
                    mma16816(acc[1][0][h * 2 + q], al[0], bA[h][2 * q], bA[h][2 * q + 1]);
                    mma16816(acc[1][1][h * 2 + q], al[1], bA[h][2 * q], bA[h][2 * q + 1]);
                }

            // pass 4: ang += xh * angL
            {
                uint32_t bL[2][4];
                ldsm_x4(bL[0], wbL + kw);
                ldsm_x4(bL[1], wbL + MI_W + kw);
                #pragma unroll
                for (int h = 0; h < 2; ++h)
                    #pragma unroll
                    for (int q = 0; q < 2; ++q) {
                        mma16816(acc[1][0][h * 2 + q], ah[0], bL[h][2 * q], bL[h][2 * q + 1]);
                        mma16816(acc[1][1][h * 2 + q], ah[1], bL[h][2 * q], bL[h][2 * q + 1]);
                    }
            }
        }

        // ---- CP_WAIT (own T+1 group done) then barrier: staging visible,
        //      all panel reads done ----
        CP_WAIT0();
        GBAR128(bar_id);

        // ---- convert T+1: scratch f32 -> panels (tiny, per-chunk fused) ----
        const int nxt = tile + TILE_STRIDE;
        if (nxt < N_TILES) {
            #pragma unroll
            for (int i = 0; i < 8; ++i) {
                uint32_t c = (cv_c0 + 4u * (uint32_t)i) & 31u;
                float4 v;
                lds128(v, scratch + (cv_row * 32u + c) * 16u);
                uint32_t h0, l0, h1, l1;
                cvt_hl(v.x, v.y, h0, l0);
                cvt_hl(v.z, v.w, h1, l1);
                uint32_t d = cv_row * 272u + c * 8u;
                sts64(xh_base + d, h0, h1);
                sts64(xl_base + d, l0, l1);
            }
        }
        GBAR128(bar_id);   // scratch reads done; panels ready

        // ---- stage T+2 into scratch (latency hides under epi + next kloop) --
        const int nx2 = tile + 2 * TILE_STRIDE;
        if (nx2 < N_TILES) {
            const float* src = x + (size_t)nx2 * 32 * 128;
            #pragma unroll
            for (int j = 0; j < 8; ++j) {
                int chunk = j * 128 + rbtid;
                CP_ASYNC16(scratch + (uint32_t)chunk * 16u, src + (size_t)chunk * 4);
            }
            CP_COMMIT();
        }

        // ---- epilogue: out = cos(ang + bias) * exp(log)  (no barrier after;
        //      warps drift straight into the next k-loop) ----
        #pragma unroll
        for (int mi = 0; mi < 2; ++mi) {
            size_t r0 = (size_t)tile * 32 + mi * 16 + (lane >> 2);
            float* p0 = out + r0 * 128 + colbase + 2 * (lane & 3);
            #pragma unroll
            for (int nc = 0; nc < 4; ++nc) {
                const float* A = acc[1][mi][nc];
                const float* G = acc[0][mi][nc];
                float2 o0, o1;
                o0.x = __cosf(A[0] + bs0[nc]) * __expf(G[0]);
                o0.y = __cosf(A[1] + bs1[nc]) * __expf(G[1]);
                o1.x = __cosf(A[2] + bs0[nc]) * __expf(G[2]);
                o1.y = __cosf(A[3] + bs1[nc]) * __expf(G[3]);
                *(float2*)(p0 + nc * 8) = o0;
                *(float2*)(p0 + nc * 8 + 8 * 128) = o1;
            }
        }
    }
}

// ---------------------------------------------------------------------------
extern "C" void kernel_launch(void* const* d_in, const int* in_sizes, int n_in,
                              void* d_out, int out_size) {
    const float* x    = (const float*)d_in[0];
    const float* wr   = (const float*)d_in[1];
    const float* wi   = (const float*)d_in[2];
    const float* bias = (const float*)d_in[3];
    float* out = (float*)d_out;
    (void)in_sizes; (void)n_in; (void)out_size;

    cudaFuncSetAttribute(ces_main, cudaFuncAttributeMaxDynamicSharedMemorySize,
                         (int)SMEM_BYTES);

    ces_prep<<<64, 256>>>(wr, wi);
    ces_main<<<GRID_CTAS, 384, SMEM_BYTES>>>(x, bias, out);
}

// round 16
// speedup vs baseline: 1.1531x; 1.0167x over previous
#include <cuda_runtime.h>
#include <cuda_fp16.h>
#include <cstdint>

// ============================================================================
// CESLayer: out[b,o] = cos( x@angle^T + bias ) * exp( x@log|w|^T )
// B=262144, I=O=128.  fp16 mma.sync (exact products):
//   angle = xh*angH + xl*angH + xh*angL ; logmag = xh*logH   (4 passes)
// R14: 512 threads = 4 row-blocks x 4 warps (one warp of each rb per SMSP,
//      independent barrier domains -> drift/mutual hiding), 32-row tiles,
//      lean panel k-loop (no cvt), X staged via LDG->regs->panels (no f32
//      scratch smem; LDG latency hidden under the MUFU epilogue).
// ============================================================================

#define N_TILES   8192            // 32-row tiles
#define GRID_CTAS 148
#define N_RB      4
#define TILE_STRIDE (N_RB * GRID_CTAS)    // 592
#define LDS_STRIDE 136

// smem: panels rb at rb*17408 (xh 8704 | xl 8704), then W, then bias
#define OFF_W     69632u          // 3 mats * 34816: [angH, angL, logH] fp16
#define OFF_BIAS  174080u
#define SMEM_BYTES 174592u

__device__ __align__(16) __half g_W[3 * 16384];

// ---------------------------------------------------------------------------
__device__ __forceinline__ uint32_t smem_u32(const void* p) {
    uint32_t a;
    asm("{ .reg .u64 t; cvta.to.shared.u64 t, %1; cvt.u32.u64 %0, t; }"
        : "=r"(a) : "l"(p));
    return a;
}

__device__ __forceinline__ uint32_t h2u(__half2 v) {
    return *reinterpret_cast<uint32_t*>(&v);
}

__device__ __forceinline__ void ldsm_x4(uint32_t r[4], uint32_t addr) {
    asm volatile("ldmatrix.sync.aligned.m8n8.x4.shared.b16 {%0,%1,%2,%3}, [%4];"
                 : "=r"(r[0]), "=r"(r[1]), "=r"(r[2]), "=r"(r[3]) : "r"(addr));
}

__device__ __forceinline__ void sts64(uint32_t addr, uint32_t r0, uint32_t r1) {
    asm volatile("st.shared.v2.b32 [%0], {%1,%2};"
                 :: "r"(addr), "r"(r0), "r"(r1) : "memory");
}

__device__ __forceinline__ void mma16816(float c[4], const uint32_t a[4],
                                         uint32_t b0, uint32_t b1) {
    asm volatile(
        "mma.sync.aligned.m16n8k16.row.col.f32.f16.f16.f32 "
        "{%0,%1,%2,%3}, {%4,%5,%6,%7}, {%8,%9}, {%0,%1,%2,%3};"
        : "+f"(c[0]), "+f"(c[1]), "+f"(c[2]), "+f"(c[3])
        : "r"(a[0]), "r"(a[1]), "r"(a[2]), "r"(a[3]), "r"(b0), "r"(b1));
}

// split one f32 pair into fp16 hi + lo packed halves
__device__ __forceinline__ void cvt_hl(float xx, float yy, uint32_t& h, uint32_t& l) {
    __half2 hh = __floats2half2_rn(xx, yy);
    __half2 ll = __floats2half2_rn(xx - __low2float(hh), yy - __high2float(hh));
    h = h2u(hh);
    l = h2u(ll);
}

#define GBAR128(id) asm volatile("bar.sync %0, 128;" :: "r"(id) : "memory")

// ---------------------------------------------------------------------------
__global__ void ces_prep(const float* __restrict__ wr, const float* __restrict__ wi) {
    int idx = blockIdx.x * blockDim.x + threadIdx.x;
    if (idx >= 16384) return;
    float a = wr[idx], b = wi[idx];
    float la = 0.5f * logf(fmaf(a, a, b * b));
    float an = atan2f(b, a);
    __half anh = __float2half_rn(an);
    __half anl = __float2half_rn(an - __half2float(anh));
    g_W[0 * 16384 + idx] = anh;                   // angH
    g_W[1 * 16384 + idx] = anl;                   // angL
    g_W[2 * 16384 + idx] = __float2half_rn(la);   // logH
}

// ---------------------------------------------------------------------------
// 16 warps = 4 row-blocks x 4 warps (rb = wid>>2 -> warps of one rb sit on
// the 4 different SMSPs; each SMSP hosts one warp from each rb domain).
// rb tile: 32 rows x 128 cols; warp: wn = wid&3 (32-col slice), mi = 16-row halves.
// ---------------------------------------------------------------------------
__global__ void __launch_bounds__(512, 1)
ces_main(const float* __restrict__ x, const float* __restrict__ bias,
         float* __restrict__ out) {
    extern __shared__ char smem[];
    const uint32_t sb = smem_u32(smem);
    const int tid   = threadIdx.x;
    const int lane  = tid & 31;
    const int wid   = tid >> 5;
    const int rb    = wid >> 2;       // row-block 0..3
    const int wn    = wid & 3;        // 32-col slice

    const uint32_t xh_base = sb + (uint32_t)rb * 17408u;   // fp16 32x136
    const uint32_t xl_base = xh_base + 8704u;

    // X staging mapping: per warp rows {wn, wn+4, ..., wn+28}, lane = 16B chunk
    // LDG: v[j] = x[tile*32 + (j*4+wn)] [lane*4 .. lane*4+3]
    // STS: panel row j*4+wn, byte off lane*8 (4 fp16)
    const uint32_t cv_d0 = (uint32_t)wn * 272u + (uint32_t)lane * 8u;

    // ---- copy W (3 x 128 x 128 fp16) into padded smem ----
    if (tid < 384) {
        int r = tid;
        const uint4* srcw = (const uint4*)(g_W + r * 128);
        uint4* dst = (uint4*)(smem + OFF_W + ((uint32_t)(r >> 7) * 17408u +
                                              (uint32_t)(r & 127) * LDS_STRIDE) * 2u);
        #pragma unroll
        for (int j = 0; j < 16; ++j) dst[j] = srcw[j];
    }
    if (tid < 128) ((float*)(smem + OFF_BIAS))[tid] = bias[tid];

    // ---- prologue: first tile's x -> regs -> panels ----
    int tile = blockIdx.x * N_RB + rb;
    {
        const float* src = x + (size_t)tile * 32 * 128 + (size_t)wn * 128 + lane * 4;
        float4 v[8];
        #pragma unroll
        for (int j = 0; j < 8; ++j)
            v[j] = __ldg((const float4*)(src + (size_t)j * 512));
        #pragma unroll
        for (int j = 0; j < 8; ++j) {
            uint32_t h0, l0, h1, l1;
            cvt_hl(v[j].x, v[j].y, h0, l0);
            cvt_hl(v[j].z, v[j].w, h1, l1);
            uint32_t d = cv_d0 + (uint32_t)j * 1088u;   // 4 rows * 272
            sts64(xh_base + d, h0, h1);
            sts64(xl_base + d, l0, l1);
        }
    }
    __syncthreads();

    // bias pairs in registers (tile-invariant)
    const int colbase = wn * 32;
    float bs0[4], bs1[4];
    {
        const float* sbias = (const float*)(smem + OFF_BIAS);
        #pragma unroll
        for (int nc = 0; nc < 4; ++nc) {
            int c = colbase + nc * 8 + 2 * (lane & 3);
            bs0[nc] = sbias[c];
            bs1[nc] = sbias[c + 1];
        }
    }

    // A-side ldmatrix bases (panels, 136 fp16 stride)
    const uint32_t aoff = ((uint32_t)(lane & 15) * LDS_STRIDE +
                           (uint32_t)((lane >> 4) * 8)) * 2u;
    const uint32_t a_h  = xh_base + aoff;
    const uint32_t a_l  = xl_base + aoff;
    const uint32_t MI_A = 16u * LDS_STRIDE * 2u;

    // B-side ldmatrix bases
    const uint32_t boff = ((uint32_t)(colbase + ((lane & 7) | ((lane & 16) >> 1))) * LDS_STRIDE +
                          (uint32_t)(lane & 8)) * 2u;
    const uint32_t MI_W = 16u * LDS_STRIDE * 2u;
    const uint32_t wbA = sb + OFF_W + boff;           // angH
    const uint32_t wbL = wbA + 34816u;                // angL
    const uint32_t wbG = wbA + 69632u;                // logH

    const int bar_id = rb + 1;

    for (; tile < N_TILES; tile += TILE_STRIDE) {
        float acc[2][2][4][4];   // [mat(log/ang)][mi][nc][4]
        #pragma unroll
        for (int m = 0; m < 2; ++m)
            #pragma unroll
            for (int i = 0; i < 2; ++i)
                #pragma unroll
                for (int n = 0; n < 4; ++n)
                    #pragma unroll
                    for (int q = 0; q < 4; ++q) acc[m][i][n][q] = 0.f;

        // ---- k-loop: 10 ldsm + 32 HMMA per k (verified pass order) ----
        #pragma unroll
        for (int k = 0; k < 8; ++k) {
            const uint32_t kw = (uint32_t)k * 32u;

            uint32_t ah[2][4], al[2][4];
            ldsm_x4(ah[0], a_h + kw);
            ldsm_x4(ah[1], a_h + MI_A + kw);
            ldsm_x4(al[0], a_l + kw);
            ldsm_x4(al[1], a_l + MI_A + kw);

            uint32_t bA[2][4];
            ldsm_x4(bA[0], wbA + kw);
            ldsm_x4(bA[1], wbA + MI_W + kw);

            // pass 1: ang += xh * angH
            #pragma unroll
            for (int h = 0; h < 2; ++h)
                #pragma unroll
                for (int q = 0; q < 2; ++q) {
                    mma16816(acc[1][0][h * 2 + q], ah[0], bA[h][2 * q], bA[h][2 * q + 1]);
                    mma16816(acc[1][1][h * 2 + q], ah[1], bA[h][2 * q], bA[h][2 * q + 1]);
                }

            // pass 2: log += xh * logH
            {
                uint32_t bG[2][4];
                ldsm_x4(bG[0], wbG + kw);
                ldsm_x4(bG[1], wbG + MI_W + kw);
                #pragma unroll
                for (int h = 0; h < 2; ++h)
                    #pragma unroll
                    for (int q = 0; q < 2; ++q) {
                        mma16816(acc[0][0][h * 2 + q], ah[0], bG[h][2 * q], bG[h][2 * q + 1]);
                        mma16816(acc[0][1][h * 2 + q], ah[1], bG[h][2 * q], bG[h][2 * q + 1]);
                    }
            }

            // pass 3: ang += xl * angH
            #pragma unroll
            for (int h = 0; h < 2; ++h)
                #pragma unroll
                for (int q = 0; q < 2; ++q) {
                    mma16816(acc[1][0][h * 2 + q], al[0], bA[h][2 * q], bA[h][2 * q + 1]);
                    mma16816(acc[1][1][h * 2 + q], al[1], bA[h][2 * q], bA[h][2 * q + 1]);
                }

            // pass 4: ang += xh * angL
            {
                uint32_t bL[2][4];
                ldsm_x4(bL[0], wbL + kw);
                ldsm_x4(bL[1], wbL + MI_W + kw);
                #pragma unroll
                for (int h = 0; h < 2; ++h)
                    #pragma unroll
                    for (int q = 0; q < 2; ++q) {
                        mma16816(acc[1][0][h * 2 + q], ah[0], bL[h][2 * q], bL[h][2 * q + 1]);
                        mma16816(acc[1][1][h * 2 + q], ah[1], bL[h][2 * q], bL[h][2 * q + 1]);
                    }
            }
        }

        // ---- LDG next tile's x into registers (latency hides under epilogue) -
        const int nxt = tile + TILE_STRIDE;
        float4 v[8];
        if (nxt < N_TILES) {
            const float* src = x + (size_t)nxt * 32 * 128 + (size_t)wn * 128 + lane * 4;
            #pragma unroll
            for (int j = 0; j < 8; ++j)
                v[j] = __ldg((const float4*)(src + (size_t)j * 512));
        }

        // ---- epilogue: out = cos(ang + bias) * exp(log) ----
        #pragma unroll
        for (int mi = 0; mi < 2; ++mi) {
            size_t r0 = (size_t)tile * 32 + mi * 16 + (lane >> 2);
            float* p0 = out + r0 * 128 + colbase + 2 * (lane & 3);
            #pragma unroll
            for (int nc = 0; nc < 4; ++nc) {
                const float* A = acc[1][mi][nc];
                const float* G = acc[0][mi][nc];
                float2 o0, o1;
                o0.x = __cosf(A[0] + bs0[nc]) * __expf(G[0]);
                o0.y = __cosf(A[1] + bs1[nc]) * __expf(G[1]);
                o1.x = __cosf(A[2] + bs0[nc]) * __expf(G[2]);
                o1.y = __cosf(A[3] + bs1[nc]) * __expf(G[3]);
                *(float2*)(p0 + nc * 8) = o0;
                *(float2*)(p0 + nc * 8 + 8 * 128) = o1;
            }
        }

        GBAR128(bar_id);   // all rb warps done reading panels (kloop finished)

        // ---- convert: regs -> panels (tiny) ----
        if (nxt < N_TILES) {
            #pragma unroll
            for (int j = 0; j < 8; ++j) {
                uint32_t h0, l0, h1, l1;
                cvt_hl(v[j].x, v[j].y, h0, l0);
                cvt_hl(v[j].z, v[j].w, h1, l1);
                uint32_t d = cv_d0 + (uint32_t)j * 1088u;
                sts64(xh_base + d, h0, h1);
                sts64(xl_base + d, l0, l1);
            }
        }
        GBAR128(bar_id);   // panels ready
    }
}

// ---------------------------------------------------------------------------
extern "C" void kernel_launch(void* const* d_in, const int* in_sizes, int n_in,
                              void* d_out, int out_size) {
    const float* x    = (const float*)d_in[0];
    const float* wr   = (const float*)d_in[1];
    const float* wi   = (const float*)d_in[2];
    const float* bias = (const float*)d_in[3];
    float* out = (float*)d_out;
    (void)in_sizes; (void)n_in; (void)out_size;

    cudaFuncSetAttribute(ces_main, cudaFuncAttributeMaxDynamicSharedMemorySize,
                         (int)SMEM_BYTES);

    ces_prep<<<64, 256>>>(wr, wi);
    ces_main<<<GRID_CTAS, 512, SMEM_BYTES>>>(x, bias, out);
}